// round 17
// baseline (speedup 1.0000x reference)
#include <cuda_runtime.h>

#define NS 8192
#define NH 64
#define CC 64
#define TILES 4

// Scratch (allocation-free rule: __device__ globals)
__device__ float g_X1[NS * CC];
__device__ float g_X2[NS * CC];
__device__ unsigned short g_bits[NS * 512];   // 8 MB packed mask

// ---------------------------------------------------------------------------
// Kernel 1 (R16 double-buffered version — best known at ~31 us).
// ---------------------------------------------------------------------------
__global__ void __launch_bounds__(256) prep_kernel(
    const float* __restrict__ Hp, const float* __restrict__ w1,
    const float* __restrict__ W2, const float* __restrict__ w3)
{
    __shared__ float t_sm[TILES][64];
    const int tid  = threadIdx.x;
    const int lane = tid & 31;

    ((float*)t_sm)[tid] = 0.f;   // 256 floats == TILES*64

    const float4* base = (const float4*)(Hp + (size_t)(blockIdx.x * TILES) * (CC * NH));
    float4 v[2][4];
    #pragma unroll
    for (int k = 0; k < 4; k++) v[0][k] = __ldcs(base + tid + 256 * k);

    const int h0 = (tid & 15) * 4;
    const int c0 = tid >> 4;
    const float w3v0 = __ldg(w3 + h0),     w3v1 = __ldg(w3 + h0 + 1);
    const float w3v2 = __ldg(w3 + h0 + 2), w3v3 = __ldg(w3 + h0 + 3);
    float w1c[4];
    #pragma unroll
    for (int k = 0; k < 4; k++) w1c[k] = __ldg(w1 + c0 + 16 * k);

    __syncthreads();   // t_sm init visible before atomics

    #pragma unroll
    for (int p = 0; p < TILES; p++) {
        const int cur = p & 1;
        if (p + 1 < TILES) {
            #pragma unroll
            for (int k = 0; k < 4; k++)
                v[cur ^ 1][k] = __ldcs(base + (p + 1) * 1024 + tid + 256 * k);
        }

        float tq0 = 0.f, tq1 = 0.f, tq2 = 0.f, tq3 = 0.f;
        #pragma unroll
        for (int k = 0; k < 4; k++) {
            tq0 += v[cur][k].x * w1c[k];  tq1 += v[cur][k].y * w1c[k];
            tq2 += v[cur][k].z * w1c[k];  tq3 += v[cur][k].w * w1c[k];

            float d = v[cur][k].x * w3v0 + v[cur][k].y * w3v1
                    + v[cur][k].z * w3v2 + v[cur][k].w * w3v3;
            #pragma unroll
            for (int o = 8; o; o >>= 1) d += __shfl_xor_sync(0xffffffffu, d, o);
            if ((lane & 15) == 0)
                g_X2[(size_t)(blockIdx.x * TILES + p) * CC + c0 + 16 * k] = d;
        }
        tq0 += __shfl_xor_sync(0xffffffffu, tq0, 16);
        tq1 += __shfl_xor_sync(0xffffffffu, tq1, 16);
        tq2 += __shfl_xor_sync(0xffffffffu, tq2, 16);
        tq3 += __shfl_xor_sync(0xffffffffu, tq3, 16);
        if (lane < 16) {
            atomicAdd(&t_sm[p][h0],     tq0);
            atomicAdd(&t_sm[p][h0 + 1], tq1);
            atomicAdd(&t_sm[p][h0 + 2], tq2);
            atomicAdd(&t_sm[p][h0 + 3], tq3);
        }
    }
    __syncthreads();

    const int cp   = tid >> 2;
    const int part = tid & 3;
    const float4* w2v = (const float4*)(W2 + cp * NH + part * 16);
    float4 w[4];
    #pragma unroll
    for (int j = 0; j < 4; j++) w[j] = __ldg(&w2v[j]);

    #pragma unroll
    for (int p = 0; p < TILES; p++) {
        const float* tp = &t_sm[p][part * 16];
        float acc = 0.f;
        #pragma unroll
        for (int j = 0; j < 4; j++)
            acc += w[j].x * tp[4*j] + w[j].y * tp[4*j+1]
                 + w[j].z * tp[4*j+2] + w[j].w * tp[4*j+3];
        acc += __shfl_xor_sync(0xffffffffu, acc, 1);
        acc += __shfl_xor_sync(0xffffffffu, acc, 2);
        if (part == 0)
            g_X1[(size_t)(blockIdx.x * TILES + p) * CC + cp] = acc;
    }
}

// ---------------------------------------------------------------------------
// Kernel 2: pure-stream mask packer. One CTA (512 thr) per row; thread tid
// packs its 16 elements (uint4 vi = tid + k*512, elems 4vi..4vi+3) into one
// ushort — bit (4k+q) <=> element (tid + k*512)*4 + q — matching row_kernel's
// per-thread decode exactly. No smem, no barriers, fire-and-forget store.
// ---------------------------------------------------------------------------
__global__ void __launch_bounds__(512) pack_kernel(
    const unsigned int* __restrict__ mask)
{
    const int s   = blockIdx.x;
    const int tid = threadIdx.x;
    const uint4* mv = (const uint4*)(mask + (size_t)s * NS);

    unsigned int b = 0;
    #pragma unroll
    for (int k = 0; k < 4; k++) {
        uint4 u = __ldcs(mv + tid + k * 512);
        b |= (u.x ? 1u : 0u) << (4 * k);
        b |= (u.y ? 1u : 0u) << (4 * k + 1);
        b |= (u.z ? 1u : 0u) << (4 * k + 2);
        b |= (u.w ? 1u : 0u) << (4 * k + 3);
    }
    g_bits[s * 512 + tid] = (unsigned short)b;
}

// ---------------------------------------------------------------------------
// Kernel 3: R12/R16 row_kernel with the 256 MB mask read replaced by one
// L2-hot ushort bitmask load per thread. Structure otherwise identical.
// ---------------------------------------------------------------------------
#define MAXM 2048   // binomial(8192, 0.01): mean 82, std 9 — huge margin

__global__ void __launch_bounds__(512) row_kernel(
    const float* __restrict__ V, const float* __restrict__ B,
    float* __restrict__ out)
{
    __shared__ int   idxs[MAXM];    // 8 KB compacted column indices
    __shared__ float e_c[MAXM];     // 8 KB compacted e values
    __shared__ float x1s[64];
    __shared__ float rowsum;
    __shared__ int   cnt;

    const int s    = blockIdx.x;
    const int tid  = threadIdx.x;
    const int lane = tid & 31;
    const int wid  = tid >> 5;
    const size_t rowoff = (size_t)s * NS;

    if (tid == 0) { cnt = 0; rowsum = 1e-6f; }
    if (tid < 64) x1s[tid] = g_X1[(size_t)s * CC + tid];

    // One packed-bits load per thread (8 MB total, L2-hot from pack_kernel)
    unsigned int bm = g_bits[s * 512 + tid];

    // Fire-and-forget streaming zero write of the output row
    float4* out4 = (float4*)(out + rowoff);
    const float4 z4 = make_float4(0.f, 0.f, 0.f, 0.f);
    #pragma unroll
    for (int k = 0; k < 4; k++) __stcs(out4 + tid + k * 512, z4);

    __syncthreads();   // cnt/rowsum/x1s visible

    // --- Phase A: warp-aggregated compaction from bitmask -------------------
    const int nh = __popc(bm);

    int incl = nh;
    #pragma unroll
    for (int o = 1; o < 32; o <<= 1) {
        int t = __shfl_up_sync(0xffffffffu, incl, o);
        if (lane >= o) incl += t;
    }
    int wbase = 0;
    if (lane == 31 && incl > 0) wbase = atomicAdd(&cnt, incl);
    wbase = __shfl_sync(0xffffffffu, wbase, 31);

    int pos = wbase + incl - nh;   // exclusive prefix within warp
    unsigned int rem = bm;
    while (rem) {
        const int bb = __ffs(rem) - 1;
        rem &= rem - 1;
        // bit (4k+q) -> element (tid + k*512)*4 + q
        idxs[pos++] = (tid + (bb >> 2) * 512) * 4 + (bb & 3);
    }
    __syncthreads();
    const int m = cnt;

    // --- Phase B: half-warp per element ------------------------------------
    const int half = lane >> 4;                       // 0 or 1
    const int hl   = lane & 15;
    const unsigned hmask = 0xFFFFu << (half * 16);
    const float4 x1v = *(const float4*)(x1s + hl * 4);
    float lsum = 0.f;

    for (int el = wid * 2 + half; el < m; el += 32) {
        const int j = idxs[el];
        const float bb = __ldcs(B + rowoff + j);      // once-only: evict-first
        const float vv = __ldcs(V + rowoff + j);
        const float4 xv = __ldg((const float4*)(g_X2 + (size_t)j * CC) + hl);
        float p = xv.x * x1v.x + xv.y * x1v.y + xv.z * x1v.z + xv.w * x1v.w;
        #pragma unroll
        for (int o = 8; o; o >>= 1) p += __shfl_xor_sync(hmask, p, o);
        if (hl == 0) {
            const float sg = 1.f / (1.f + expf(-(p + bb)));
            const float ev = expf(vv * sg);
            e_c[el] = ev;
            lsum += ev;
        }
    }

    // --- Row sum: warp reduce + one smem atomic per warp --------------------
    #pragma unroll
    for (int o = 16; o; o >>= 1) lsum += __shfl_down_sync(0xffffffffu, lsum, o);
    if (lane == 0 && lsum != 0.f) atomicAdd(&rowsum, lsum);
    __syncthreads();

    // --- Sparse scatter of scaled values over the zeros ---------------------
    const float inv = 1.f / rowsum;
    for (int el = tid; el < m; el += 512)
        __stcs(out + rowoff + idxs[el], e_c[el] * inv);
}

extern "C" void kernel_launch(void* const* d_in, const int* in_sizes, int n_in,
                              void* d_out, int out_size)
{
    (void)in_sizes; (void)n_in; (void)out_size;
    const float* Hp  = (const float*)d_in[0];
    const float* w1  = (const float*)d_in[1];
    const float* W2  = (const float*)d_in[2];
    const float* w3  = (const float*)d_in[3];
    const float* V   = (const float*)d_in[4];
    const float* B   = (const float*)d_in[5];
    const unsigned int* mask = (const unsigned int*)d_in[6];
    float* out = (float*)d_out;

    prep_kernel<<<NS / TILES, 256>>>(Hp, w1, W2, w3);
    pack_kernel<<<NS, 512>>>(mask);
    row_kernel<<<NS, 512>>>(V, B, out);
}